// round 13
// baseline (speedup 1.0000x reference)
#include <cuda_runtime.h>
#include <cuda_fp16.h>

// FastRotation — warp-autonomous half2 pair tile, v7 (base = R10).
// vs R10: (a) zero-fill only BORDER rows (two contiguous z-slabs + 8 y-border
// rows, ~6 phases vs 12) — interior rows are fully defined by staging because
// edge elements (x==0 / x==4) store whole half2 words; (b) staging slot index
// decoded by mul-shift ALU (drops the g_b table LDG). Sampling identical to
// R10: packed-fp16 base table, a+w*(b-a) HFMA2 lerps.
// Tile: slot (z,y,xp) at word ((z+1)*7+(y+1))*7+xp = 49z+7y+56+xp holds fp16
// x-pair (v[z][y][xp-1], v[z][y][xp]); z,y in [-1..5], xp in [0..5].

#define KVOL  125
#define ZSTR  49          // words per z-slab (7 rows * 7 words)
#define YSTR  7           // words per row
#define WORDS 344         // 343 padded to float4 multiple
#define WPB   8           // warps (= volumes) per block
#define TPB   (WPB * 32)

// fp16 bit patterns for lattice coord c = 0.5*idx - 1, idx in 0..4
#define HP(i) ((i)==0 ? 0xBC00u : (i)==1 ? 0xB800u : (i)==2 ? 0x0000u : \
               (i)==3 ? 0x3800u : 0x3C00u)
// Packed base for point p = i*25 + j*5 + l : u.x = half(bi)|half(bj)<<16, u.y = half(bl)
#define UV(i,j,l) { HP(i) | (HP(j) << 16), HP(l) }
#define U5(i,j)  UV(i,j,0), UV(i,j,1), UV(i,j,2), UV(i,j,3), UV(i,j,4)
#define U25(i)   U5(i,0), U5(i,1), U5(i,2), U5(i,3), U5(i,4)
__device__ const uint2 g_bh[128] = { U25(0), U25(1), U25(2), U25(3), U25(4) };

__global__ __launch_bounds__(TPB) void fast_rotation_kernel(
    const float* __restrict__ vol,      // [N,125]
    const float* __restrict__ theta_v,  // [N,3]
    const float* __restrict__ theta,    // [N]
    float* __restrict__ out,            // [N,125]
    int N)
{
    __shared__ __half2 sp[WPB * WORDS];

    const int w    = threadIdx.x >> 5;
    const int lane = threadIdx.x & 31;
    const int n    = blockIdx.x * WPB + w;
    if (n >= N) return;

    __half2* tile  = &sp[w * WORDS];
    __half*  tileh = (__half*)tile;

    // ---- Border-only zero-fill ----
    // Slab A: words [0,56)   = zp=0 block + row (zp=1,yp=0)        -> t4[0..13]
    // Slab B: words [284,344)= zp=6 block + row (zp=5,yp=6) (+2 interior
    //         words 284..285, later overwritten by staging)        -> t4[71..85]
    {
        float4* t4 = (float4*)tile;
        const float4 z4 = make_float4(0.f, 0.f, 0.f, 0.f);
        if (lane < 29) t4[lane < 14 ? lane : lane + 57] = z4;
    }
    // Remaining 8 y-border rows (7 words each = 56 words):
    // r=0..7 -> (zp,yb): (1,6),(2,0),(2,6),(3,0),(3,6),(4,0),(4,6),(5,0)
    {
        const __half2 zh = __float2half2_rn(0.0f);
        #pragma unroll
        for (int rr = 0; rr < 2; ++rr) {
            const int idx = lane + 32 * rr;
            if (idx < 56) {
                const int r  = (idx * 147) >> 10;   // idx / 7
                const int c  = idx - 7 * r;
                const int zp = (r + 3) >> 1;
                const int yb = (r & 1) ? 0 : 6;
                tile[49 * zp + 7 * yb + c] = zh;
            }
        }
    }
    __syncwarp();

    // ---- Staging: 2 stores per element; edge elements store whole words ----
    const float* vsrc = vol + n * KVOL;
    #pragma unroll
    for (int q = 0; q < 4; ++q) {
        const int m = lane + 32 * q;
        if (m < KVOL) {
            const float v = __ldcs(vsrc + m);
            const __half h = __float2half_rn(v);
            const int z   = (m * 41) >> 10;       // m / 25
            const int rem = m - 25 * z;
            const int y   = (rem * 205) >> 10;    // rem / 5
            const int x   = rem - 5 * y;
            const int b   = 49 * z + 7 * y + x + 56;   // slot word
            if (x == 0) tile[b] = __floats2half2_rn(0.0f, v);  // word0 fully
            else        tileh[2 * b + 1] = h;                  // .y of word b
            if (x == 4) tile[b + 1] = __floats2half2_rn(v, 0.0f); // word5 fully
            else        tileh[2 * b + 2] = h;                  // .x of word b+1
        }
    }

    // Rodrigues matrix (pre-scaled by 2), redundant per lane. |v|^2 == 1.
    const float tx = theta_v[n * 3 + 0];
    const float ty = theta_v[n * 3 + 1];
    const float tz = theta_v[n * 3 + 2];
    const float inv = rsqrtf(fmaxf(tx * tx + ty * ty + tz * tz, 1e-24f));
    const float vx = tx * inv, vy = ty * inv, vz = tz * inv;
    const float a  = theta[n];
    const float ss = 2.0f * __sinf(a);
    const float cs = 2.0f * (1.0f - __cosf(a));
    const float R00 = 2.0f + cs * (vx * vx - 1.0f);
    const float R01 = -ss * vz + cs * (vx * vy);
    const float R02 =  ss * vy + cs * (vx * vz);
    const float R10 =  ss * vz + cs * (vy * vx);
    const float R11 = 2.0f + cs * (vy * vy - 1.0f);
    const float R12 = -ss * vx + cs * (vy * vz);
    const float R20 = -ss * vy + cs * (vz * vx);
    const float R21 =  ss * vx + cs * (vz * vy);
    const float R22 = 2.0f + cs * (vz * vz - 1.0f);

    __syncwarp();   // tile visible warp-wide

    float* dst = out + n * KVOL;

    #pragma unroll
    for (int q = 0; q < 4; ++q) {
        const int p = lane + 32 * q;
        if (p < KVOL) {
            const uint2 u = __ldg(&g_bh[p]);
            const __half2 hij = *reinterpret_cast<const __half2*>(&u.x);
            const float2 bij  = __half22float2(hij);
            const float  bl   = __half2float(*reinterpret_cast<const __half*>(&u.y));

            // pixel coords: (grid + 1) * 2 = base . (2R) + 2
            const float x = fmaf(bij.x, R00, fmaf(bij.y, R10, fmaf(bl, R20, 2.0f)));
            const float y = fmaf(bij.x, R01, fmaf(bij.y, R11, fmaf(bl, R21, 2.0f)));
            const float z = fmaf(bij.x, R02, fmaf(bij.y, R12, fmaf(bl, R22, 2.0f)));

            const int x0 = __float2int_rd(x);
            const int y0 = __float2int_rd(y);
            const int z0 = __float2int_rd(z);
            const float wx = x - (float)x0;
            const float wy = y - (float)y0;
            const float wz = z - (float)z0;

            // In-range iff base cell in [-1,4] per axis; else exact zero.
            const bool ok = ((unsigned)(x0 + 1) <= 5u) &
                            ((unsigned)(y0 + 1) <= 5u) &
                            ((unsigned)(z0 + 1) <= 5u);

            float r = 0.0f;
            if (ok) {
                // slot (z0,y0,x0+1): word = (z0+1)*49 + (y0+1)*7 + x0+1
                const int wd = z0 * ZSTR + y0 * YSTR + x0 + (ZSTR + YSTR + 1);
                const __half2 f00 = tile[wd];
                const __half2 f10 = tile[wd + YSTR];
                const __half2 f01 = tile[wd + ZSTR];
                const __half2 f11 = tile[wd + ZSTR + YSTR];

                const __half2 wyb = __float2half2_rn(wy);
                const __half2 wzb = __float2half2_rn(wz);

                const __half2 a0 = __hfma2(__hsub2(f10, f00), wyb, f00);
                const __half2 a1 = __hfma2(__hsub2(f11, f01), wyb, f01);
                const __half2 g  = __hfma2(__hsub2(a1, a0), wzb, a0);

                const float2 gf = __half22float2(g);
                r = fmaf(wx, gf.y - gf.x, gf.x);
            }
            dst[p] = r;
        }
    }
}

extern "C" void kernel_launch(void* const* d_in, const int* in_sizes, int n_in,
                              void* d_out, int out_size)
{
    const float* vol     = (const float*)d_in[0];  // input_filter [N,5,5,5]
    const float* theta_v = (const float*)d_in[1];  // [N,3]
    const float* theta   = (const float*)d_in[2];  // [N]
    float* out = (float*)d_out;

    const int N = in_sizes[2];                     // theta has N elements
    const int blocks = (N + WPB - 1) / WPB;
    fast_rotation_kernel<<<blocks, TPB>>>(vol, theta_v, theta, out, N);
}

// round 14
// speedup vs baseline: 1.4672x; 1.4672x over previous
#include <cuda_runtime.h>
#include <cuda_fp16.h>

// FastRotation — warp-autonomous half2 pair tile, v8 (frame = R10 champion).
// Single delta vs R10: staging slot index decoded by branch-free mul-shift
// (IMAD/SHF straight-line; proven in R7/R8) instead of the g_b table LDG —
// removes 4 LDG wavefronts/warp from the saturated L1 pipe. Everything else
// identical to R10: full branch-free zero-fill, 2x STS.16 staging, packed
// fp16 base-coord table, a+w*(b-a) HFMA2 lerps, vv==1 Rodrigues.
// Tile: slot (z,y,xp) at word 49z+7y+xp+56 holds fp16 x-pair
// (v[z][y][xp-1], v[z][y][xp]); z,y in [-1..5], xp in [0..5]; borders zero.

#define KVOL  125
#define ZSTR  49          // words per z-slab (7 rows * 7 words)
#define YSTR  7           // words per row
#define WORDS 344         // 343 padded to float4 multiple
#define WPB   8           // warps (= volumes) per block
#define TPB   (WPB * 32)

// fp16 bit patterns for lattice coord c = 0.5*idx - 1, idx in 0..4
#define HP(i) ((i)==0 ? 0xBC00u : (i)==1 ? 0xB800u : (i)==2 ? 0x0000u : \
               (i)==3 ? 0x3800u : 0x3C00u)
// Packed base for point p = i*25 + j*5 + l : u.x = half(bi)|half(bj)<<16, u.y = half(bl)
#define UV(i,j,l) { HP(i) | (HP(j) << 16), HP(l) }
#define U5(i,j)  UV(i,j,0), UV(i,j,1), UV(i,j,2), UV(i,j,3), UV(i,j,4)
#define U25(i)   U5(i,0), U5(i,1), U5(i,2), U5(i,3), U5(i,4)
__device__ const uint2 g_bh[128] = { U25(0), U25(1), U25(2), U25(3), U25(4) };

__global__ __launch_bounds__(TPB) void fast_rotation_kernel(
    const float* __restrict__ vol,      // [N,125]
    const float* __restrict__ theta_v,  // [N,3]
    const float* __restrict__ theta,    // [N]
    float* __restrict__ out,            // [N,125]
    int N)
{
    __shared__ __half2 sp[WPB * WORDS];

    const int w    = threadIdx.x >> 5;
    const int lane = threadIdx.x & 31;
    const int n    = blockIdx.x * WPB + w;
    if (n >= N) return;

    __half2* tile  = &sp[w * WORDS];
    __half*  tileh = (__half*)tile;

    // Hoist rotation-parameter loads (broadcast; overlaps zero-fill latency)
    const float tx = theta_v[n * 3 + 0];
    const float ty = theta_v[n * 3 + 1];
    const float tz = theta_v[n * 3 + 2];
    const float th = theta[n];

    // Zero-fill: 344 half2 = 1376 B = 86 float4 (branch-free pattern)
    {
        float4* t4 = (float4*)tile;
        const float4 z4 = make_float4(0.f, 0.f, 0.f, 0.f);
        t4[lane]      = z4;
        t4[lane + 32] = z4;
        if (lane < 86 - 64) t4[lane + 64] = z4;
    }
    __syncwarp();

    // Scatter volume into pair tile (fp16): element m = z*25+y*5+x lands as
    // .y of slot b and .x of slot b+1, b = 49z+7y+x+56 (mul-shift decode,
    // straight-line). Distinct half-words; no races; no branches.
    const float* vsrc = vol + n * KVOL;
    #pragma unroll
    for (int q = 0; q < 4; ++q) {
        const int m = lane + 32 * q;
        if (m < KVOL) {
            const __half h = __float2half_rn(__ldcs(vsrc + m));
            const int z   = (m * 41) >> 10;       // m / 25   (exact, m < 1024)
            const int rem = m - 25 * z;
            const int y   = (rem * 205) >> 10;    // rem / 5  (exact, rem < 125)
            const int x   = rem - 5 * y;
            const int b   = 49 * z + 7 * y + x + 56;
            tileh[2 * b + 1] = h;
            tileh[2 * b + 2] = h;
        }
    }

    // Rodrigues matrix (pre-scaled by 2), redundant per lane. |v|^2 == 1.
    const float inv = rsqrtf(fmaxf(tx * tx + ty * ty + tz * tz, 1e-24f));
    const float vx = tx * inv, vy = ty * inv, vz = tz * inv;
    const float ss = 2.0f * __sinf(th);
    const float cs = 2.0f * (1.0f - __cosf(th));
    const float R00 = 2.0f + cs * (vx * vx - 1.0f);
    const float R01 = -ss * vz + cs * (vx * vy);
    const float R02 =  ss * vy + cs * (vx * vz);
    const float R10 =  ss * vz + cs * (vy * vx);
    const float R11 = 2.0f + cs * (vy * vy - 1.0f);
    const float R12 = -ss * vx + cs * (vy * vz);
    const float R20 = -ss * vy + cs * (vz * vx);
    const float R21 =  ss * vx + cs * (vz * vy);
    const float R22 = 2.0f + cs * (vz * vz - 1.0f);

    __syncwarp();   // tile visible warp-wide

    float* dst = out + n * KVOL;

    #pragma unroll
    for (int q = 0; q < 4; ++q) {
        const int p = lane + 32 * q;
        if (p < KVOL) {
            const uint2 u = __ldg(&g_bh[p]);
            const __half2 hij = *reinterpret_cast<const __half2*>(&u.x);
            const float2 bij  = __half22float2(hij);
            const float  bl   = __half2float(*reinterpret_cast<const __half*>(&u.y));

            // pixel coords: (grid + 1) * 2 = base . (2R) + 2
            const float x = fmaf(bij.x, R00, fmaf(bij.y, R10, fmaf(bl, R20, 2.0f)));
            const float y = fmaf(bij.x, R01, fmaf(bij.y, R11, fmaf(bl, R21, 2.0f)));
            const float z = fmaf(bij.x, R02, fmaf(bij.y, R12, fmaf(bl, R22, 2.0f)));

            const int x0 = __float2int_rd(x);
            const int y0 = __float2int_rd(y);
            const int z0 = __float2int_rd(z);
            const float wx = x - (float)x0;
            const float wy = y - (float)y0;
            const float wz = z - (float)z0;

            // In-range iff base cell in [-1,4] per axis; else exact zero.
            const bool ok = ((unsigned)(x0 + 1) <= 5u) &
                            ((unsigned)(y0 + 1) <= 5u) &
                            ((unsigned)(z0 + 1) <= 5u);

            float r = 0.0f;
            if (ok) {
                // slot (z0,y0,x0+1): word = 49*z0 + 7*y0 + x0 + 57
                const int wd = z0 * ZSTR + y0 * YSTR + x0 + (ZSTR + YSTR + 1);
                const __half2 f00 = tile[wd];
                const __half2 f10 = tile[wd + YSTR];
                const __half2 f01 = tile[wd + ZSTR];
                const __half2 f11 = tile[wd + ZSTR + YSTR];

                const __half2 wyb = __float2half2_rn(wy);
                const __half2 wzb = __float2half2_rn(wz);

                const __half2 a0 = __hfma2(__hsub2(f10, f00), wyb, f00);
                const __half2 a1 = __hfma2(__hsub2(f11, f01), wyb, f01);
                const __half2 g  = __hfma2(__hsub2(a1, a0), wzb, a0);

                const float2 gf = __half22float2(g);
                r = fmaf(wx, gf.y - gf.x, gf.x);
            }
            dst[p] = r;
        }
    }
}

extern "C" void kernel_launch(void* const* d_in, const int* in_sizes, int n_in,
                              void* d_out, int out_size)
{
    const float* vol     = (const float*)d_in[0];  // input_filter [N,5,5,5]
    const float* theta_v = (const float*)d_in[1];  // [N,3]
    const float* theta   = (const float*)d_in[2];  // [N]
    float* out = (float*)d_out;

    const int N = in_sizes[2];                     // theta has N elements
    const int blocks = (N + WPB - 1) / WPB;
    fast_rotation_kernel<<<blocks, TPB>>>(vol, theta_v, theta, out, N);
}